// round 2
// baseline (speedup 1.0000x reference)
#include <cuda_runtime.h>
#include <math.h>

#define OUT_DIM 4096
#define DPC     16
#define NCOLS   (OUT_DIM * DPC)   // 65536
#define BATCH   512

// Per-column boost factors, computed once per launch (batch-invariant).
__device__ float g_bf[NCOLS];

__global__ void bf_kernel(const float* __restrict__ duty_cycle,
                          const float* __restrict__ boost_strength) {
    int k = blockIdx.x * blockDim.x + threadIdx.x;
    if (k < NCOLS) {
        const float target_density = (float)OUT_DIM / (float)NCOLS;  // 0.0625
        float bs = boost_strength[0];
        g_bf[k] = expf((target_density - duty_cycle[k]) * bs);
    }
}

__global__ void __launch_bounds__(256)
dkw_kernel(const float* __restrict__ x, float* __restrict__ out) {
    int idx = blockIdx.x * blockDim.x + threadIdx.x;   // 0 .. BATCH*OUT_DIM-1
    int b = idx >> 12;                                  // / OUT_DIM
    int i = idx & (OUT_DIM - 1);

    const float* xr = x + (size_t)b * NCOLS;
    int wbase = i * (DPC - 1);                          // 15*i  (window start)

    // Argmax over boosted window [15i, 15i+16), first-occurrence semantics.
    float best = -INFINITY;
    int bj = 0;
#pragma unroll
    for (int j = 0; j < DPC; ++j) {
        float v = __ldg(xr + wbase + j) * __ldg(&g_bf[wbase + j]);
        if (v > best) { best = v; bj = j; }
    }

    // Output chunk lives at non-overlapping base 16*i; only element bj is kept.
    int obase = i * DPC;
    float val = __ldg(xr + obase + bj);

    float4* o = reinterpret_cast<float4*>(out + (size_t)b * NCOLS + obase);
#pragma unroll
    for (int q = 0; q < 4; ++q) {
        float4 v;
        v.x = (bj == 4 * q + 0) ? val : 0.0f;
        v.y = (bj == 4 * q + 1) ? val : 0.0f;
        v.z = (bj == 4 * q + 2) ? val : 0.0f;
        v.w = (bj == 4 * q + 3) ? val : 0.0f;
        o[q] = v;
    }
}

extern "C" void kernel_launch(void* const* d_in, const int* in_sizes, int n_in,
                              void* d_out, int out_size) {
    const float* x  = (const float*)d_in[0];
    const float* dc = (const float*)d_in[1];
    const float* bs = (const float*)d_in[2];
    float* out = (float*)d_out;

    bf_kernel<<<NCOLS / 256, 256>>>(dc, bs);
    dkw_kernel<<<(BATCH * OUT_DIM) / 256, 256>>>(x, out);
}

// round 3
// speedup vs baseline: 1.4838x; 1.4838x over previous
#include <cuda_runtime.h>
#include <math.h>

#define OUT_DIM 4096
#define DPC     16
#define NCOLS   (OUT_DIM * DPC)   // 65536
#define BATCH   512
#define WPB     256               // windows per block
#define WSPAN   3844              // padded window span floats (need 15*255+16=3841)
#define WSPAN4  961               // float4 count covering 3844 floats

__global__ void __launch_bounds__(256)
dkw_kernel(const float* __restrict__ x,
           const float* __restrict__ duty_cycle,
           const float* __restrict__ boost_strength,
           float* __restrict__ out) {
    __shared__ float wprod[WSPAN];
    __shared__ int   s_bj[WPB];
    __shared__ float s_val[WPB];

    const int tid = threadIdx.x;
    const int b = blockIdx.x >> 4;        // batch row
    const int w = blockIdx.x & 15;        // window-block within row

    const float bs = __ldg(boost_strength);
    const float td = (float)OUT_DIM / (float)NCOLS;   // 0.0625

    // ---- Stage boosted window span: coalesced float4 loads, product to SMEM ----
    const size_t rowoff = (size_t)b * NCOLS;
    const int W0 = 3840 * w;              // 15 * 256 * w, 16B-aligned (x3840w*4)
    const float4* xw4 = reinterpret_cast<const float4*>(x + rowoff + W0);
    const float4* dc4 = reinterpret_cast<const float4*>(duty_cycle + W0);
    float4* wp4 = reinterpret_cast<float4*>(wprod);

#pragma unroll
    for (int t = tid; t < WSPAN4; t += WPB) {
        float4 xv = xw4[t];
        float4 d  = dc4[t];
        float4 p;
        p.x = xv.x * expf((td - d.x) * bs);
        p.y = xv.y * expf((td - d.y) * bs);
        p.z = xv.z * expf((td - d.z) * bs);
        p.w = xv.w * expf((td - d.w) * bs);
        wp4[t] = p;
    }
    __syncthreads();

    // ---- Argmax over boosted window: stride-15 LDS (conflict-free) ----
    const int wb = 15 * tid;
    float best = -INFINITY;
    int bj = 0;
#pragma unroll
    for (int j = 0; j < DPC; ++j) {
        float v = wprod[wb + j];
        if (v > best) { best = v; bj = j; }
    }

    // ---- Kept value from the non-overlapping output chunk ----
    const int O0 = 4096 * w;
    float val = __ldg(x + rowoff + O0 + 16 * tid + bj);

    s_bj[tid]  = bj;
    s_val[tid] = val;
    __syncthreads();

    // ---- Fully coalesced output write: 1024 float4 per block ----
    float4* o4 = reinterpret_cast<float4*>(out + rowoff + O0);
#pragma unroll
    for (int q = 0; q < 4; ++q) {
        int f  = tid + WPB * q;           // float4 index 0..1023
        int c  = f >> 2;                  // local chunk (window) index
        int j0 = (f & 3) << 2;            // first j covered by this float4
        int   bjc = s_bj[c];
        float vc  = s_val[c];
        float4 v;
        v.x = (bjc == j0 + 0) ? vc : 0.0f;
        v.y = (bjc == j0 + 1) ? vc : 0.0f;
        v.z = (bjc == j0 + 2) ? vc : 0.0f;
        v.w = (bjc == j0 + 3) ? vc : 0.0f;
        o4[f] = v;
    }
}

extern "C" void kernel_launch(void* const* d_in, const int* in_sizes, int n_in,
                              void* d_out, int out_size) {
    const float* x  = (const float*)d_in[0];
    const float* dc = (const float*)d_in[1];
    const float* bs = (const float*)d_in[2];
    float* out = (float*)d_out;

    dkw_kernel<<<BATCH * (OUT_DIM / WPB), WPB>>>(x, dc, bs, out);
}

// round 4
// speedup vs baseline: 1.5929x; 1.0735x over previous
#include <cuda_runtime.h>
#include <math.h>

#define OUT_DIM 4096
#define DPC     16
#define NCOLS   (OUT_DIM * DPC)   // 65536
#define BATCH   512
#define WPB     256               // windows (output chunks) per block
#define WSPAN4  961               // float4 count covering window span (3841 floats)

// Per-column boost factors, batch-invariant: computed once per launch.
__device__ float g_bf[NCOLS];

__global__ void bf_kernel(const float* __restrict__ duty_cycle,
                          const float* __restrict__ boost_strength) {
    int k = blockIdx.x * blockDim.x + threadIdx.x;
    const float td = (float)OUT_DIM / (float)NCOLS;  // 0.0625
    float bs = boost_strength[0];
    g_bf[k] = expf((td - duty_cycle[k]) * bs);
}

__global__ void __launch_bounds__(256)
dkw_kernel(const float* __restrict__ x, float* __restrict__ out) {
    __shared__ float prod[WSPAN4 * 4];   // boosted window span
    __shared__ int   s_bj[WPB];

    const int tid = threadIdx.x;
    const int b = blockIdx.x >> 4;        // batch row (consecutive blocks share row -> L2 reuse)
    const int w = blockIdx.x & 15;        // window-block within row

    const size_t rowoff = (size_t)b * NCOLS;
    const int W0 = 3840 * w;              // window span start (16B aligned)
    const int O0 = 4096 * w;              // output chunk span start

    // ---- Stage boosted products: fully coalesced float4 loads ----
    const float4* xw4 = reinterpret_cast<const float4*>(x + rowoff + W0);
    const float4* bf4 = reinterpret_cast<const float4*>(g_bf + W0);
    float4* p4 = reinterpret_cast<float4*>(prod);
#pragma unroll
    for (int t = tid; t < WSPAN4; t += WPB) {
        float4 xv = xw4[t];
        float4 bv = bf4[t];
        float4 p;
        p.x = xv.x * bv.x;
        p.y = xv.y * bv.y;
        p.z = xv.z * bv.z;
        p.w = xv.w * bv.w;
        p4[t] = p;
    }
    __syncthreads();

    // ---- Argmax over window [15*tid, 15*tid+16): stride-15 LDS, conflict-free ----
    const int wb = 15 * tid;
    float best = -INFINITY;
    int bj = 0;
#pragma unroll
    for (int j = 0; j < DPC; ++j) {
        float v = prod[wb + j];
        if (v > best) { best = v; bj = j; }
    }
    s_bj[tid] = bj;
    __syncthreads();

    // ---- Output: coalesced re-read of x chunk (L1/L2 hot) + mask + coalesced store ----
    const float4* xc4 = reinterpret_cast<const float4*>(x + rowoff + O0);
    float4* o4 = reinterpret_cast<float4*>(out + rowoff + O0);
#pragma unroll
    for (int q = 0; q < 4; ++q) {
        int f  = tid + WPB * q;           // float4 index 0..1023
        int c  = f >> 2;                  // window index within block
        int j0 = (f & 3) << 2;            // first j covered by this float4
        int bjc = s_bj[c];
        float4 xv = xc4[f];
        float4 v;
        v.x = (bjc == j0 + 0) ? xv.x : 0.0f;
        v.y = (bjc == j0 + 1) ? xv.y : 0.0f;
        v.z = (bjc == j0 + 2) ? xv.z : 0.0f;
        v.w = (bjc == j0 + 3) ? xv.w : 0.0f;
        o4[f] = v;
    }
}

extern "C" void kernel_launch(void* const* d_in, const int* in_sizes, int n_in,
                              void* d_out, int out_size) {
    const float* x  = (const float*)d_in[0];
    const float* dc = (const float*)d_in[1];
    const float* bs = (const float*)d_in[2];
    float* out = (float*)d_out;

    bf_kernel<<<NCOLS / 256, 256>>>(dc, bs);
    dkw_kernel<<<BATCH * (OUT_DIM / WPB), WPB>>>(x, out);
}